// round 8
// baseline (speedup 1.0000x reference)
#include <cuda_runtime.h>
#include <math.h>

#define H 1024
#define W 1024
#define BATCH 16
#define CH 3
#define NPLANE (H * W)
#define NPIX (BATCH * NPLANE)

#define G0 0.13533528323661270f  /* exp(-2)   */
#define G1 0.60653065971263342f  /* exp(-0.5) */

#define TXW 256     /* tile width (outputs)            */
#define TYH 64      /* tile height (outputs)           */
#define NT 160      /* threads per block               */
#define TXH 128     /* output column pairs per row     */
#define LW2 132     /* img float2 pairs: cols x0-4 .. x0+259 */
#define BW2 130     /* blurred pairs:    cols x0-2 .. x0+257 */
#define MAGW 260    /* s_mag floats; idx = col - x0 + 2      */

template<bool INTERIOR>
__device__ __forceinline__ void canny_body(
    const float* __restrict__ imgb,   /* img  + b*3*NPLANE */
    float* __restrict__ blb,          /* blur + b*3*NPLANE */
    float* __restrict__ out,
    int b, int x0, int y0, int t,
    float bh, float bv, float shb, float svb, float d0b, float d1b,
    float2 (*s_img2)[LW2], float2 (*s_bl2)[BW2], float (*s_mag)[MAGW])
{
    /* register rings: [channel][column 0/1] */
    float h0[CH][2], h1[CH][2], h2[CH][2], h3[CH][2], h4[CH][2];
    float hs0[CH][2], hs1[CH][2], hs2[CH][2];
    float hd0[CH][2], hd1[CH][2], hd2[CH][2];
    #pragma unroll
    for (int c = 0; c < CH; c++)
        #pragma unroll
        for (int u = 0; u < 2; u++) {
            h0[c][u] = h1[c][u] = h2[c][u] = h3[c][u] = h4[c][u] = 0.0f;
            hs0[c][u] = hs1[c][u] = hs2[c][u] = 0.0f;
            hd0[c][u] = hd1[c][u] = hd2[c][u] = 0.0f;
        }
    float pm[2]  = {0.0f, 0.0f};
    float pgx[2] = {0.0f, 0.0f};
    float pgy[2] = {0.0f, 0.0f};

    const size_t pbase = (size_t)b * NPLANE + (size_t)y0 * W + x0 + 2 * t;

    float* gm_out     = out + (size_t)3 * NPIX;
    float* orient_out = out + (size_t)4 * NPIX;
    float* thin_out   = out + (size_t)5 * NPIX;
    float* thresh_out = out + (size_t)6 * NPIX;
    float* early_out  = out + (size_t)7 * NPIX;

#define CANNY_ITER(i, DO_D)                                                      \
    {                                                                            \
        const int y_img = y0 - 4 + (i);                                          \
        const int yb = y_img - 2;                                                \
        const int ym = yb - 1;                                                   \
        const bool rAok = INTERIOR || ((y_img >= 0) && (y_img < H));             \
                                                                                 \
        /* ---- A: load img row pairs (3 channels) ---- */                       \
        if (t < LW2) {                                                           \
            if (INTERIOR) {                                                      \
                const float2* sp = (const float2*)(imgb + (size_t)y_img * W + (x0 - 4)); \
                _Pragma("unroll")                                                \
                for (int c = 0; c < CH; c++)                                     \
                    s_img2[c][t] = sp[t + c * (NPLANE / 2)];                     \
            } else {                                                             \
                const int c0 = x0 - 4 + 2 * t;                                   \
                const bool ok0 = rAok && ((unsigned)c0 < (unsigned)W);           \
                const bool ok1 = rAok && ((unsigned)(c0 + 1) < (unsigned)W);     \
                const size_t ro = rAok ? (size_t)y_img * W : 0;                  \
                _Pragma("unroll")                                                \
                for (int c = 0; c < CH; c++) {                                   \
                    const float* sc = imgb + (size_t)c * NPLANE + ro;            \
                    float v0 = ok0 ? sc[c0] : 0.0f;                              \
                    float v1 = ok1 ? sc[c0 + 1] : 0.0f;                          \
                    s_img2[c][t] = make_float2(v0, v1);                          \
                }                                                                \
            }                                                                    \
        }                                                                        \
        __syncthreads();                                                         \
                                                                                 \
        /* ---- B: h-blur pair + vertical ring -> blurred row ---- */            \
        if (t < BW2) {                                                           \
            const int j0 = x0 - 2 + 2 * t;                                       \
            const bool rBok = INTERIOR || ((yb >= 0) && (yb < H));               \
            const bool wr = (yb >= y0) && (yb < y0 + TYH) && (t >= 1) && (t <= TXH); \
            float* wp = blb + ((size_t)yb * W + j0);                             \
            _Pragma("unroll")                                                    \
            for (int c = 0; c < CH; c++) {                                       \
                const float2 p0 = s_img2[c][t];                                  \
                const float2 p1 = s_img2[c][t + 1];                              \
                const float2 p2 = s_img2[c][t + 2];                              \
                float hnA = G0 * (p0.x + p2.x) + G1 * (p0.y + p1.y) + p1.x + bh; \
                float hnB = G0 * (p0.y + p2.y) + G1 * (p1.x + p2.x) + p1.y + bh; \
                if (!INTERIOR && !rAok) { hnA = 0.0f; hnB = 0.0f; }              \
                h0[c][0] = h1[c][0]; h1[c][0] = h2[c][0]; h2[c][0] = h3[c][0];   \
                h3[c][0] = h4[c][0]; h4[c][0] = hnA;                             \
                h0[c][1] = h1[c][1]; h1[c][1] = h2[c][1]; h2[c][1] = h3[c][1];   \
                h3[c][1] = h4[c][1]; h4[c][1] = hnB;                             \
                const float BA = G0 * (h0[c][0] + h4[c][0]) + G1 * (h1[c][0] + h3[c][0]) + h2[c][0] + bv; \
                const float BB = G0 * (h0[c][1] + h4[c][1]) + G1 * (h1[c][1] + h3[c][1]) + h2[c][1] + bv; \
                float sbA = BA, sbB = BB;                                        \
                if (!INTERIOR) {                                                 \
                    if (!(rBok && (unsigned)j0 < (unsigned)W)) sbA = 0.0f;       \
                    if (!(rBok && (unsigned)(j0 + 1) < (unsigned)W)) sbB = 0.0f; \
                }                                                                \
                s_bl2[c][t] = make_float2(sbA, sbB);                             \
                if (wr) *(float2*)(wp + (size_t)c * NPLANE) = make_float2(BA, BB); \
            }                                                                    \
        }                                                                        \
        __syncthreads();                                                         \
                                                                                 \
        /* ---- C: separable sobel rings -> mag row ---- */                      \
        float nm0 = 0.0f, ngx0 = 0.0f, ngy0 = 0.0f;                              \
        float nm1 = 0.0f, ngx1 = 0.0f, ngy1 = 0.0f;                              \
        if (t <= TXH) {                                                          \
            float sA0[CH], sA1[CH], sA2[CH], sB0[CH], sB1[CH], sB2[CH];          \
            if (t < TXH) {                                                       \
                _Pragma("unroll")                                                \
                for (int c = 0; c < CH; c++) {                                   \
                    const float2 q0 = s_bl2[c][t];                               \
                    const float2 q1 = s_bl2[c][t + 1];                           \
                    const float2 q2 = s_bl2[c][t + 2];                           \
                    sA0[c] = q0.y; sA1[c] = q1.x; sA2[c] = q1.y;                 \
                    sB0[c] = q1.x; sB1[c] = q1.y; sB2[c] = q2.x;                 \
                }                                                                \
            } else {                                                             \
                _Pragma("unroll")                                                \
                for (int c = 0; c < CH; c++) {                                   \
                    const float* f = (const float*)s_bl2[c];                     \
                    sA0[c] = f[0];   sA1[c] = f[1];   sA2[c] = f[2];             \
                    sB0[c] = f[257]; sB1[c] = f[258]; sB2[c] = f[259];           \
                }                                                                \
            }                                                                    \
            _Pragma("unroll")                                                    \
            for (int c = 0; c < CH; c++) {                                       \
                float hsn = sA0[c] + 2.0f * sA1[c] + sA2[c];                     \
                float hdn = sA0[c] - sA2[c];                                     \
                hs0[c][0] = hs1[c][0]; hs1[c][0] = hs2[c][0]; hs2[c][0] = hsn;   \
                hd0[c][0] = hd1[c][0]; hd1[c][0] = hd2[c][0]; hd2[c][0] = hdn;   \
                float gxv = hd0[c][0] + 2.0f * hd1[c][0] + hd2[c][0] + shb;      \
                float gyv = hs0[c][0] - hs2[c][0] + svb;                         \
                nm0 += sqrtf(gxv * gxv + gyv * gyv);                             \
                ngx0 += gxv; ngy0 += gyv;                                        \
                hsn = sB0[c] + 2.0f * sB1[c] + sB2[c];                           \
                hdn = sB0[c] - sB2[c];                                           \
                hs0[c][1] = hs1[c][1]; hs1[c][1] = hs2[c][1]; hs2[c][1] = hsn;   \
                hd0[c][1] = hd1[c][1]; hd1[c][1] = hd2[c][1]; hd2[c][1] = hdn;   \
                gxv = hd0[c][1] + 2.0f * hd1[c][1] + hd2[c][1] + shb;            \
                gyv = hs0[c][1] - hs2[c][1] + svb;                               \
                nm1 += sqrtf(gxv * gxv + gyv * gyv);                             \
                ngx1 += gxv; ngy1 += gyv;                                        \
            }                                                                    \
            const bool rMok = INTERIOR || ((ym >= 0) && (ym < H));               \
            const int sl = (i) & 1;                                             \
            if (t < TXH) {                                                       \
                if (!INTERIOR && !rMok) { nm0 = 0.0f; nm1 = 0.0f; }              \
                ((float2*)(s_mag[sl] + 2))[t] = make_float2(nm0, nm1);           \
            } else {                                                             \
                if (!(rMok && (x0 > 0)))       nm0 = 0.0f;                       \
                if (!(rMok && (x0 + TXW < W))) nm1 = 0.0f;                       \
                s_mag[sl][1]   = nm0;                                            \
                s_mag[sl][258] = nm1;                                            \
            }                                                                    \
        }                                                                        \
        __syncthreads();                                                         \
                                                                                 \
        /* ---- D: orientation + NMS + 5 outputs ---- */                         \
        if (DO_D && (t < TXH)) {                                                 \
            const int slC = ((i) - 1) & 1;                                       \
            const int slN = (i) & 1;                                             \
            const size_t p = pbase + (size_t)((i) - 8) * W;                      \
            float om[2], oo[2], oe[2], ot[2], oh[2];                             \
            _Pragma("unroll")                                                    \
            for (int u = 0; u < 2; u++) {                                        \
                const float mag = pm[u];                                         \
                om[u] = mag;                                                     \
                float go = atan2f(pgy[u], pgx[u]) * (180.0f / 3.14159f);         \
                if (go < 0.0f) go = 360.0f + go;                                 \
                go = fmodf(go, 180.0f);                                          \
                const float orient = rintf(go / 45.0f) * 45.0f;                  \
                oo[u] = orient;                                                  \
                oe[u] = (mag < 10.0f) ? 0.0f : mag;                              \
                const int k = (int)(orient * (1.0f / 45.0f) + 0.5f);             \
                const int di = (k >= 1 && k <= 3) ? 1 : 0;                       \
                const int dj = (k < 2) ? 1 : ((k == 2) ? 0 : -1);                \
                const float bias = (k < 4) ? d0b : d1b;                          \
                const float nbv = s_mag[di ? slN : slC][2 * t + 2 + u + dj];     \
                const float val = mag - nbv + bias;                              \
                const float th = (val > 0.0f) ? mag : 0.0f;                      \
                ot[u] = th;                                                      \
                oh[u] = (th < 10.0f) ? 0.0f : th;                                \
            }                                                                    \
            *(float2*)(gm_out + p)     = make_float2(om[0], om[1]);              \
            *(float2*)(orient_out + p) = make_float2(oo[0], oo[1]);              \
            *(float2*)(early_out + p)  = make_float2(oe[0], oe[1]);              \
            *(float2*)(thin_out + p)   = make_float2(ot[0], ot[1]);              \
            *(float2*)(thresh_out + p) = make_float2(oh[0], oh[1]);              \
        }                                                                        \
        pm[0] = nm0; pgx[0] = ngx0; pgy[0] = ngy0;                               \
        pm[1] = nm1; pgx[1] = ngx1; pgy[1] = ngy1;                               \
    }

    /* warmup: rows -4..+3, no outputs (blurred gmem writes start at i=6) */
    #pragma unroll 2
    for (int i = 0; i < 8; i++) {
        CANNY_ITER(i, false);
    }
    /* steady state */
    #pragma unroll 2
    for (int i = 8; i < TYH + 8; i++) {
        CANNY_ITER(i, true);
    }
#undef CANNY_ITER
}

__global__ __launch_bounds__(NT) void canny_kernel(
    const float* __restrict__ img,
    const float* __restrict__ bh_p,  const float* __restrict__ bv_p,
    const float* __restrict__ shb_p, const float* __restrict__ svb_p,
    const float* __restrict__ d0b_p, const float* __restrict__ d1b_p,
    float* __restrict__ out)
{
    __shared__ float2 s_img2[CH][LW2];
    __shared__ float2 s_bl2[CH][BW2];
    __shared__ float  s_mag[2][MAGW];

    const int b  = blockIdx.z;
    const int x0 = blockIdx.x * TXW;
    const int y0 = blockIdx.y * TYH;
    const int t  = threadIdx.x;

    const float bh  = __ldg(bh_p),  bv  = __ldg(bv_p);
    const float shb = __ldg(shb_p), svb = __ldg(svb_p);
    const float d0b = __ldg(d0b_p), d1b = __ldg(d1b_p);

    const float* imgb = img + (size_t)b * CH * NPLANE;
    float* blb = out + (size_t)b * CH * NPLANE;

    const bool interior = (x0 >= 4) && (x0 + TXW + 4 <= W) &&
                          (y0 >= 4) && (y0 + TYH + 4 <= H);

    if (interior)
        canny_body<true >(imgb, blb, out, b, x0, y0, t,
                          bh, bv, shb, svb, d0b, d1b, s_img2, s_bl2, s_mag);
    else
        canny_body<false>(imgb, blb, out, b, x0, y0, t,
                          bh, bv, shb, svb, d0b, d1b, s_img2, s_bl2, s_mag);
}

/* ================================================================== */
extern "C" void kernel_launch(void* const* d_in, const int* in_sizes, int n_in,
                              void* d_out, int out_size)
{
    const float* img = (const float*)d_in[0];
    const float* bh  = (const float*)d_in[1];
    const float* bv  = (const float*)d_in[2];
    const float* shb = (const float*)d_in[3];
    const float* svb = (const float*)d_in[4];
    const float* d0b = (const float*)d_in[5];
    const float* d1b = (const float*)d_in[6];

    dim3 grid(W / TXW, H / TYH, BATCH);
    canny_kernel<<<grid, NT>>>(img, bh, bv, shb, svb, d0b, d1b, (float*)d_out);

    (void)in_sizes; (void)n_in; (void)out_size;
}

// round 9
// speedup vs baseline: 1.5903x; 1.5903x over previous
#include <cuda_runtime.h>
#include <math.h>

#define H 1024
#define W 1024
#define BATCH 16
#define CH 3
#define NPLANE (H * W)
#define NPIX (BATCH * NPLANE)

#define G0 0.13533528323661270f  /* exp(-2)   */
#define G1 0.60653065971263342f  /* exp(-0.5) */

#define TX 128      /* tile width (outputs)  */
#define TY 64       /* tile height (outputs) */
#define NT 160      /* threads per block     */
#define LW 136      /* img row width loaded  : cols x0-4 .. x0+131 */
#define BW 132      /* blurred row width     : cols x0-2 .. x0+129 */
#define MW2 130     /* mag cols              : x0-1 .. x0+128       */

template<bool INTERIOR>
__device__ __forceinline__ void canny_body(
    const float* __restrict__ imgb,   /* img  + b*3*NPLANE */
    float* __restrict__ blb,          /* blur + b*3*NPLANE */
    float* __restrict__ out,
    int b, int x0, int y0, int t,
    float bh, float bv, float shb, float svb, float d0b, float d1b,
    float (*s_img)[CH][LW], float (*s_bl)[CH][LW], float (*s_mag)[LW])
{
    /* register rings (single column per thread, as R7) */
    float h0[CH], h1[CH], h2[CH], h3[CH], h4[CH];            /* vertical blur */
    float hs0[CH], hs1[CH], hs2[CH];                         /* sobel h-sums  */
    float hd0[CH], hd1[CH], hd2[CH];                         /* sobel h-diffs */
    #pragma unroll
    for (int c = 0; c < CH; c++) {
        h0[c] = h1[c] = h2[c] = h3[c] = h4[c] = 0.0f;
        hs0[c] = hs1[c] = hs2[c] = 0.0f;
        hd0[c] = hd1[c] = hd2[c] = 0.0f;
    }
    float pm = 0.0f, pgx = 0.0f, pgy = 0.0f;   /* last computed mag row, own col */

    const int gxl = x0 - 4 + t;                           /* img load col   */
    const bool cAok = INTERIOR || ((unsigned)gxl < (unsigned)W);
    const int colB = x0 - 2 + t;                          /* blurred col    */
    const bool cBok = INTERIOR || ((unsigned)colB < (unsigned)W);

    /* phase-C column map: t<128 -> col x0+t, t==128 -> halo x0-1, t==129 -> halo x0+128 */
    int ib, im; bool cMok;
    if (t < TX)       { ib = t + 2;  im = t + 1;  cMok = true; }
    else if (t == TX) { ib = 1;      im = 0;      cMok = INTERIOR || (x0 > 0); }
    else              { ib = TX + 2; im = TX + 1; cMok = INTERIOR || (x0 + TX < W); }

    const size_t pbase = (size_t)b * NPLANE + (size_t)y0 * W + x0 + t;

    float* gm_out     = out + (size_t)3 * NPIX;
    float* orient_out = out + (size_t)4 * NPIX;
    float* thin_out   = out + (size_t)5 * NPIX;
    float* thresh_out = out + (size_t)6 * NPIX;
    float* early_out  = out + (size_t)7 * NPIX;

    /* ---- phase helpers (inlined lambdas) ---- */
    auto loadA = [&](int y_img, float (*si)[LW]) {
        if (t < LW) {
            if (INTERIOR) {
                const size_t ro = (size_t)y_img * W + gxl;
                #pragma unroll
                for (int c = 0; c < CH; c++)
                    si[c][t] = imgb[(size_t)c * NPLANE + ro];
            } else {
                const bool rAok = ((unsigned)y_img < (unsigned)H);
                const bool ok = rAok && cAok;
                const size_t ro = ok ? ((size_t)y_img * W + gxl) : 0;
                #pragma unroll
                for (int c = 0; c < CH; c++)
                    si[c][t] = ok ? imgb[(size_t)c * NPLANE + ro] : 0.0f;
            }
        }
    };

    auto phaseB = [&](int y_img, float (*si)[LW], float (*sb)[LW]) {
        const int yb = y_img - 2;
        if (t < BW) {
            const bool rAok = INTERIOR || ((unsigned)y_img < (unsigned)H);
            const bool rBok = INTERIOR || ((unsigned)yb < (unsigned)H);
            const bool wr = (yb >= y0) && (yb < y0 + TY) && (t >= 2) && (t < 2 + TX);
            float* wp = blb + ((size_t)yb * W + (x0 + t - 2));
            #pragma unroll
            for (int c = 0; c < CH; c++) {
                const float v0 = si[c][t],     v1 = si[c][t + 1],
                            v2 = si[c][t + 2], v3 = si[c][t + 3],
                            v4 = si[c][t + 4];
                float hn = G0 * (v0 + v4) + G1 * (v1 + v3) + v2 + bh;
                if (!INTERIOR && !rAok) hn = 0.0f;
                h0[c] = h1[c]; h1[c] = h2[c]; h2[c] = h3[c]; h3[c] = h4[c]; h4[c] = hn;
                const float B = G0 * (h0[c] + h4[c]) + G1 * (h1[c] + h3[c]) + h2[c] + bv;
                sb[c][t] = (INTERIOR || (rBok && cBok)) ? B : 0.0f;
                if (wr) wp[(size_t)c * NPLANE] = B;
            }
        }
    };

    auto phaseC = [&](int ym, float (*sb)[LW], float* mrow,
                      float& nm, float& ngx, float& ngy) {
        nm = 0.0f; ngx = 0.0f; ngy = 0.0f;
        if (t < MW2) {
            #pragma unroll
            for (int c = 0; c < CH; c++) {
                const float b0 = sb[c][ib - 1], b1 = sb[c][ib], b2 = sb[c][ib + 1];
                const float hsn = b0 + 2.0f * b1 + b2;
                const float hdn = b0 - b2;
                hs0[c] = hs1[c]; hs1[c] = hs2[c]; hs2[c] = hsn;
                hd0[c] = hd1[c]; hd1[c] = hd2[c]; hd2[c] = hdn;
                const float gxv = (hd0[c] + 2.0f * hd1[c]) + hd2[c] + shb;
                const float gyv = hs0[c] - hs2[c] + svb;
                nm += sqrtf(gxv * gxv + gyv * gyv);
                ngx += gxv; ngy += gyv;
            }
            const bool rMok = INTERIOR || ((unsigned)ym < (unsigned)H);
            if (!(rMok && cMok)) nm = 0.0f;
            mrow[im] = nm;
        }
    };

    auto phaseD = [&](int yo_off, float mag, float gx, float gy,
                      const float* magC, const float* magN) {
        if (t < TX) {
            const size_t p = pbase + (size_t)yo_off * W;

            gm_out[p] = mag;

            float go = atan2f(gy, gx) * (180.0f / 3.14159f);
            if (go < 0.0f) go = 360.0f + go;
            go = fmodf(go, 180.0f);
            const float orient = rintf(go / 45.0f) * 45.0f;
            orient_out[p] = orient;

            early_out[p] = (mag < 10.0f) ? 0.0f : mag;

            const int k = (int)(orient * (1.0f / 45.0f) + 0.5f);   /* 0..4 */
            const int di = (k >= 1 && k <= 3) ? 1 : 0;
            const int dj = (k < 2) ? 1 : ((k == 2) ? 0 : -1);
            const float bias = (k < 4) ? d0b : d1b;

            const float nbv = (di ? magN : magC)[t + 1 + dj];  /* OOB already 0 */
            const float val = mag - nbv + bias;
            const float th = (val > 0.0f) ? mag : 0.0f;
            thin_out[p]   = th;
            thresh_out[p] = (th < 10.0f) ? 0.0f : th;
        }
    };

    /* ---- main loop: 2 img rows per iteration, 3 barriers per pair ---- */
    #pragma unroll 1
    for (int ii = 0; ii < (TY + 8) / 2; ii++) {
        const int i0 = 2 * ii, i1 = 2 * ii + 1;
        const int yA = y0 - 4 + i0;        /* img rows this pair */
        const int yB = y0 - 4 + i1;

        loadA(yA, s_img[0]);
        loadA(yB, s_img[1]);
        __syncthreads();

        phaseB(yA, s_img[0], s_bl[0]);
        phaseB(yB, s_img[1], s_bl[1]);
        __syncthreads();

        float nmA, ngxA, ngyA, nmB, ngxB, ngyB;
        phaseC(yA - 3, s_bl[0], s_mag[i0 & 3], nmA, ngxA, ngyA);
        phaseC(yB - 3, s_bl[1], s_mag[i1 & 3], nmB, ngxB, ngyB);
        __syncthreads();

        if (ii >= 4) {
            /* output rows y0+i0-8 and y0+i1-8 */
            phaseD(i0 - 8, pm, pgx, pgy, s_mag[(i0 - 1) & 3], s_mag[i0 & 3]);
            phaseD(i1 - 8, nmA, ngxA, ngyA, s_mag[i0 & 3], s_mag[i1 & 3]);
        }
        pm = nmB; pgx = ngxB; pgy = ngyB;
    }
}

__global__ __launch_bounds__(NT) void canny_kernel(
    const float* __restrict__ img,
    const float* __restrict__ bh_p,  const float* __restrict__ bv_p,
    const float* __restrict__ shb_p, const float* __restrict__ svb_p,
    const float* __restrict__ d0b_p, const float* __restrict__ d1b_p,
    float* __restrict__ out)
{
    __shared__ float s_img[2][CH][LW];
    __shared__ float s_bl[2][CH][LW];
    __shared__ float s_mag[4][LW];

    const int b  = blockIdx.z;
    const int x0 = blockIdx.x * TX;
    const int y0 = blockIdx.y * TY;
    const int t  = threadIdx.x;

    const float bh  = __ldg(bh_p),  bv  = __ldg(bv_p);
    const float shb = __ldg(shb_p), svb = __ldg(svb_p);
    const float d0b = __ldg(d0b_p), d1b = __ldg(d1b_p);

    const float* imgb = img + (size_t)b * CH * NPLANE;
    float* blb = out + (size_t)b * CH * NPLANE;

    const bool interior = (x0 >= 4) && (x0 + TX + 4 <= W) &&
                          (y0 >= 4) && (y0 + TY + 4 <= H);

    if (interior)
        canny_body<true >(imgb, blb, out, b, x0, y0, t,
                          bh, bv, shb, svb, d0b, d1b, s_img, s_bl, s_mag);
    else
        canny_body<false>(imgb, blb, out, b, x0, y0, t,
                          bh, bv, shb, svb, d0b, d1b, s_img, s_bl, s_mag);
}

/* ================================================================== */
extern "C" void kernel_launch(void* const* d_in, const int* in_sizes, int n_in,
                              void* d_out, int out_size)
{
    const float* img = (const float*)d_in[0];
    const float* bh  = (const float*)d_in[1];
    const float* bv  = (const float*)d_in[2];
    const float* shb = (const float*)d_in[3];
    const float* svb = (const float*)d_in[4];
    const float* d0b = (const float*)d_in[5];
    const float* d1b = (const float*)d_in[6];

    dim3 grid(W / TX, H / TY, BATCH);
    canny_kernel<<<grid, NT>>>(img, bh, bv, shb, svb, d0b, d1b, (float*)d_out);

    (void)in_sizes; (void)n_in; (void)out_size;
}

// round 12
// speedup vs baseline: 1.7395x; 1.0938x over previous
#include <cuda_runtime.h>
#include <math.h>

#define H 1024
#define W 1024
#define BATCH 16
#define CH 3
#define NPLANE (H * W)
#define NPIX (BATCH * NPLANE)

#define G0 0.13533528323661270f  /* exp(-2)   */
#define G1 0.60653065971263342f  /* exp(-0.5) */
#define T1C 0.41421356237f       /* tan(22.5 deg) */
#define T2C 2.41421356237f       /* tan(67.5 deg) */
#define BANDEPS 1e-3f
#define WEDGE   1e-4f            /* near-pi wedge (ref wraps past 180) */

#define TX 128      /* tile width (outputs)  */
#define TY 64       /* tile height (outputs) */
#define NT 160      /* threads per block     */
#define LW 136      /* img row width loaded  : cols x0-4 .. x0+131 */
#define BW 132      /* blurred row width     : cols x0-2 .. x0+129 */
#define MW2 130     /* mag cols              : x0-1 .. x0+128       */

template<bool INTERIOR>
__device__ __forceinline__ void canny_body(
    const float* __restrict__ imgb,   /* img  + b*3*NPLANE */
    float* __restrict__ blb,          /* blur + b*3*NPLANE */
    float* __restrict__ out,
    int b, int x0, int y0, int t,
    float bh, float bv, float shb, float svb, float d0b, float d1b,
    float (*s_img)[CH][LW], float (*s_bl)[CH][LW], float (*s_mag)[LW])
{
    /* register rings (single column per thread) */
    float h0[CH], h1[CH], h2[CH], h3[CH], h4[CH];            /* vertical blur */
    float hs0[CH], hs1[CH], hs2[CH];                         /* sobel h-sums  */
    float hd0[CH], hd1[CH], hd2[CH];                         /* sobel h-diffs */
    #pragma unroll
    for (int c = 0; c < CH; c++) {
        h0[c] = h1[c] = h2[c] = h3[c] = h4[c] = 0.0f;
        hs0[c] = hs1[c] = hs2[c] = 0.0f;
        hd0[c] = hd1[c] = hd2[c] = 0.0f;
    }
    float pm = 0.0f, pgx = 0.0f, pgy = 0.0f;   /* last computed mag row, own col */

    const int gxl = x0 - 4 + t;                           /* img load col   */
    const bool cAok = INTERIOR || ((unsigned)gxl < (unsigned)W);
    const int colB = x0 - 2 + t;                          /* blurred col    */
    const bool cBok = INTERIOR || ((unsigned)colB < (unsigned)W);

    /* phase-C column map: t<128 -> col x0+t, t==128 -> halo x0-1, t==129 -> halo x0+128 */
    int ib, im; bool cMok;
    if (t < TX)       { ib = t + 2;  im = t + 1;  cMok = true; }
    else if (t == TX) { ib = 1;      im = 0;      cMok = INTERIOR || (x0 > 0); }
    else              { ib = TX + 2; im = TX + 1; cMok = INTERIOR || (x0 + TX < W); }

    const size_t pbase = (size_t)b * NPLANE + (size_t)y0 * W + x0 + t;

    float* gm_out     = out + (size_t)3 * NPIX;
    float* orient_out = out + (size_t)4 * NPIX;
    float* thin_out   = out + (size_t)5 * NPIX;
    float* thresh_out = out + (size_t)6 * NPIX;
    float* early_out  = out + (size_t)7 * NPIX;

    auto loadA = [&](int y_img, float (*si)[LW]) {
        if (t < LW) {
            if (INTERIOR) {
                const size_t ro = (size_t)y_img * W + gxl;
                #pragma unroll
                for (int c = 0; c < CH; c++)
                    si[c][t] = imgb[(size_t)c * NPLANE + ro];
            } else {
                const bool rAok = ((unsigned)y_img < (unsigned)H);
                const bool ok = rAok && cAok;
                const size_t ro = ok ? ((size_t)y_img * W + gxl) : 0;
                #pragma unroll
                for (int c = 0; c < CH; c++)
                    si[c][t] = ok ? imgb[(size_t)c * NPLANE + ro] : 0.0f;
            }
        }
    };

    auto phaseB = [&](int y_img, float (*si)[LW], float (*sb)[LW]) {
        const int yb = y_img - 2;
        if (t < BW) {
            const bool rAok = INTERIOR || ((unsigned)y_img < (unsigned)H);
            const bool rBok = INTERIOR || ((unsigned)yb < (unsigned)H);
            const bool wr = (yb >= y0) && (yb < y0 + TY) && (t >= 2) && (t < 2 + TX);
            float* wp = blb + ((size_t)yb * W + (x0 + t - 2));
            #pragma unroll
            for (int c = 0; c < CH; c++) {
                const float v0 = si[c][t],     v1 = si[c][t + 1],
                            v2 = si[c][t + 2], v3 = si[c][t + 3],
                            v4 = si[c][t + 4];
                float hn = G0 * (v0 + v4) + G1 * (v1 + v3) + v2 + bh;
                if (!INTERIOR && !rAok) hn = 0.0f;
                h0[c] = h1[c]; h1[c] = h2[c]; h2[c] = h3[c]; h3[c] = h4[c]; h4[c] = hn;
                const float B = G0 * (h0[c] + h4[c]) + G1 * (h1[c] + h3[c]) + h2[c] + bv;
                sb[c][t] = (INTERIOR || (rBok && cBok)) ? B : 0.0f;
                if (wr) wp[(size_t)c * NPLANE] = B;
            }
        }
    };

    auto phaseC = [&](int ym, float (*sb)[LW], float* mrow,
                      float& nm, float& ngx, float& ngy) {
        nm = 0.0f; ngx = 0.0f; ngy = 0.0f;
        if (t < MW2) {
            #pragma unroll
            for (int c = 0; c < CH; c++) {
                const float b0 = sb[c][ib - 1], b1 = sb[c][ib], b2 = sb[c][ib + 1];
                const float hsn = b0 + 2.0f * b1 + b2;
                const float hdn = b0 - b2;
                hs0[c] = hs1[c]; hs1[c] = hs2[c]; hs2[c] = hsn;
                hd0[c] = hd1[c]; hd1[c] = hd2[c]; hd2[c] = hdn;
                const float gxv = (hd0[c] + 2.0f * hd1[c]) + hd2[c] + shb;
                const float gyv = hs0[c] - hs2[c] + svb;
                nm += sqrtf(gxv * gxv + gyv * gyv);
                ngx += gxv; ngy += gyv;
            }
            const bool rMok = INTERIOR || ((unsigned)ym < (unsigned)H);
            if (!(rMok && cMok)) nm = 0.0f;
            mrow[im] = nm;
        }
    };

    auto phaseD = [&](int yo_off, float mag, float gx, float gy,
                      const float* magC, const float* magN) {
        if (t < TX) {
            const size_t p = pbase + (size_t)yo_off * W;

            gm_out[p] = mag;

            /* --- orientation: comparator fast path, exact fallback near
               boundaries AND in the near-pi wedge (reference's 180/3.14159
               scale wraps angles within ~2.6e-6 rad of +-pi past 180) --- */
            float ax = gx, ay = gy;
            if (ay < 0.0f) { ax = -ax; ay = -ay; }
            const float pxm = fabsf(ax);
            const float r1 = T1C * pxm;
            const float r2 = T2C * pxm;
            const bool nearb =
                (gx < 0.0f && fabsf(gy) <= WEDGE * (-gx)) ||      /* near-pi wedge */
                (fabsf(ay - r1) <= BANDEPS * (ay + r1)) ||
                (fabsf(ay - r2) <= BANDEPS * (ay + r2)) ||
                (ay == 0.0f && ax <= 0.0f);
            int k; float orient;
            if (__builtin_expect(nearb, 0)) {
                /* exact reference pipeline (matches R7) */
                float go = atan2f(gy, gx) * (180.0f / 3.14159f);
                if (go < 0.0f) go = 360.0f + go;
                go = fmodf(go, 180.0f);
                orient = rintf(go / 45.0f) * 45.0f;
                k = (int)(orient * (1.0f / 45.0f) + 0.5f);
            } else {
                if (ay >= r2)      k = 2;
                else if (ay >= r1) k = (ax > 0.0f) ? 1 : 3;
                else               k = (ax > 0.0f) ? 0 : 4;
                orient = 45.0f * (float)k;
            }
            orient_out[p] = orient;

            early_out[p] = (mag < 10.0f) ? 0.0f : mag;

            const int di = (k >= 1 && k <= 3) ? 1 : 0;
            const int dj = (k < 2) ? 1 : ((k == 2) ? 0 : -1);
            const float bias = (k < 4) ? d0b : d1b;

            const float nbv = (di ? magN : magC)[t + 1 + dj];  /* OOB already 0 */
            const float val = mag - nbv + bias;
            const float th = (val > 0.0f) ? mag : 0.0f;
            thin_out[p]   = th;
            thresh_out[p] = (th < 10.0f) ? 0.0f : th;
        }
    };

    /* ---- main loop: 2 img rows per iteration, 3 barriers per pair ---- */
    #pragma unroll 1
    for (int ii = 0; ii < (TY + 8) / 2; ii++) {
        const int i0 = 2 * ii, i1 = 2 * ii + 1;
        const int yA = y0 - 4 + i0;
        const int yB = y0 - 4 + i1;

        loadA(yA, s_img[0]);
        loadA(yB, s_img[1]);
        __syncthreads();

        phaseB(yA, s_img[0], s_bl[0]);
        phaseB(yB, s_img[1], s_bl[1]);
        __syncthreads();

        float nmA, ngxA, ngyA, nmB, ngxB, ngyB;
        phaseC(yA - 3, s_bl[0], s_mag[i0 & 3], nmA, ngxA, ngyA);
        phaseC(yB - 3, s_bl[1], s_mag[i1 & 3], nmB, ngxB, ngyB);
        __syncthreads();

        if (ii >= 4) {
            phaseD(i0 - 8, pm, pgx, pgy, s_mag[(i0 - 1) & 3], s_mag[i0 & 3]);
            phaseD(i1 - 8, nmA, ngxA, ngyA, s_mag[i0 & 3], s_mag[i1 & 3]);
        }
        pm = nmB; pgx = ngxB; pgy = ngyB;
    }
}

__global__ __launch_bounds__(NT) void canny_kernel(
    const float* __restrict__ img,
    const float* __restrict__ bh_p,  const float* __restrict__ bv_p,
    const float* __restrict__ shb_p, const float* __restrict__ svb_p,
    const float* __restrict__ d0b_p, const float* __restrict__ d1b_p,
    float* __restrict__ out)
{
    __shared__ float s_img[2][CH][LW];
    __shared__ float s_bl[2][CH][LW];
    __shared__ float s_mag[4][LW];

    const int b  = blockIdx.z;
    const int x0 = blockIdx.x * TX;
    const int y0 = blockIdx.y * TY;
    const int t  = threadIdx.x;

    const float bh  = __ldg(bh_p),  bv  = __ldg(bv_p);
    const float shb = __ldg(shb_p), svb = __ldg(svb_p);
    const float d0b = __ldg(d0b_p), d1b = __ldg(d1b_p);

    const float* imgb = img + (size_t)b * CH * NPLANE;
    float* blb = out + (size_t)b * CH * NPLANE;

    const bool interior = (x0 >= 4) && (x0 + TX + 4 <= W) &&
                          (y0 >= 4) && (y0 + TY + 4 <= H);

    if (interior)
        canny_body<true >(imgb, blb, out, b, x0, y0, t,
                          bh, bv, shb, svb, d0b, d1b, s_img, s_bl, s_mag);
    else
        canny_body<false>(imgb, blb, out, b, x0, y0, t,
                          bh, bv, shb, svb, d0b, d1b, s_img, s_bl, s_mag);
}

/* ================================================================== */
extern "C" void kernel_launch(void* const* d_in, const int* in_sizes, int n_in,
                              void* d_out, int out_size)
{
    const float* img = (const float*)d_in[0];
    const float* bh  = (const float*)d_in[1];
    const float* bv  = (const float*)d_in[2];
    const float* shb = (const float*)d_in[3];
    const float* svb = (const float*)d_in[4];
    const float* d0b = (const float*)d_in[5];
    const float* d1b = (const float*)d_in[6];

    dim3 grid(W / TX, H / TY, BATCH);
    canny_kernel<<<grid, NT>>>(img, bh, bv, shb, svb, d0b, d1b, (float*)d_out);

    (void)in_sizes; (void)n_in; (void)out_size;
}